// round 3
// baseline (speedup 1.0000x reference)
#include <cuda_runtime.h>
#include <math.h>

#define B_DIM   4096
#define C_DIM   5000
#define G4      1250                 // float4 groups per row
#define THREADS 1024
#define BLOCKS  148                  // one persistent block per SM, single wave
#define GPT     2                    // ceil(1250/1024)
#define MAX_LR  28                   // ceil(4096/148)

#define CR_BLOCKS  40
#define CR_THREADS 128

// per-block column partials (plain stores, no atomics, no pre-zeroing needed)
__device__ float  g_colp_neg[BLOCKS * C_DIM];   // 2.96 MB
__device__ float  g_colp_pos[BLOCKS * C_DIM];   // 2.96 MB
__device__ float  g_blk_rowloss[BLOCKS];
__device__ double g_col_loss;
__device__ unsigned int g_done;

__device__ __forceinline__ float softplus_f(float z) {
    return (z > 20.f) ? z : log1pf(__expf(z));
}

__global__ __launch_bounds__(THREADS, 1)
void twl_main_kernel(const float* __restrict__ logits,
                     const int*   __restrict__ targets) {
    __shared__ float s_n[MAX_LR * 32];
    __shared__ float s_p[MAX_LR * 32];
    __shared__ float s_loss[MAX_LR];

    const int t    = threadIdx.x;
    const int warp = t >> 5;
    const int lane = t & 31;

    if (blockIdx.x == 0 && t == 0) {   // reset accumulators for col_reduce
        g_col_loss = 0.0;
        g_done     = 0u;
    }

    // register-resident column partials: thread t owns float4-groups t, t+1024
    float cn[GPT][4], cp[GPT][4];
    #pragma unroll
    for (int j = 0; j < GPT; ++j)
        #pragma unroll
        for (int k = 0; k < 4; ++k) { cn[j][k] = 0.f; cp[j][k] = 0.f; }

    int lr = 0;
    for (int row = blockIdx.x; row < B_DIM; row += BLOCKS, ++lr) {
        const float4* __restrict__ lrow =
            reinterpret_cast<const float4*>(logits + (size_t)row * C_DIM);
        const int4* __restrict__ trow =
            reinterpret_cast<const int4*>(targets + (size_t)row * C_DIM);

        float rn = 0.f, rp = 0.f;

        #pragma unroll
        for (int j = 0; j < GPT; ++j) {
            const int g = t + j * THREADS;
            if (g < G4) {
                const float4 x  = lrow[g];
                const int4   tg = trow[g];

                #define PROC(XX, TT, K)                                       \
                do {                                                          \
                    const bool pos = ((TT) == 1);                             \
                    const bool neg = ((TT) == 0);                             \
                    const float a  = (XX) * (pos ? -0.25f : 1.0f);            \
                    const float e  = __expf(a);                               \
                    const float en = neg ? e : 0.f;                           \
                    const float ep = pos ? e : 0.f;                           \
                    rn += en; rp += ep;                                       \
                    cn[j][K] += en; cp[j][K] += ep;                           \
                } while (0)

                PROC(x.x, tg.x, 0);
                PROC(x.y, tg.y, 1);
                PROC(x.z, tg.z, 2);
                PROC(x.w, tg.w, 3);
                #undef PROC
            }
        }

        // warp-only reduce (no barrier): rows pipeline freely
        #pragma unroll
        for (int o = 16; o > 0; o >>= 1) {
            rn += __shfl_down_sync(0xffffffffu, rn, o);
            rp += __shfl_down_sync(0xffffffffu, rp, o);
        }
        if (lane == 0) {
            s_n[lr * 32 + warp] = rn;
            s_p[lr * 32 + warp] = rp;
        }
    }

    const int nrows = lr;
    __syncthreads();                  // the ONLY barrier before final reduce

    // warp w finishes row w: 32 warp-partials -> row loss
    if (warp < nrows) {
        float vn = s_n[warp * 32 + lane];
        float vp = s_p[warp * 32 + lane];
        #pragma unroll
        for (int o = 16; o > 0; o >>= 1) {
            vn += __shfl_down_sync(0xffffffffu, vn, o);
            vp += __shfl_down_sync(0xffffffffu, vp, o);
        }
        if (lane == 0) {
            float loss = 0.f;
            if (vn > 0.f && vp > 0.f) {
                const float z = __logf(vn) + 4.f * __logf(vp);
                loss = softplus_f(z);
            }
            s_loss[warp] = loss;
        }
    }
    __syncthreads();
    if (warp == 0) {
        float v = (lane < nrows) ? s_loss[lane] : 0.f;
        #pragma unroll
        for (int o = 16; o > 0; o >>= 1)
            v += __shfl_down_sync(0xffffffffu, v, o);
        if (lane == 0) g_blk_rowloss[blockIdx.x] = v;
    }

    // flush column partials: plain coalesced float4 stores
    #pragma unroll
    for (int j = 0; j < GPT; ++j) {
        const int g = t + j * THREADS;
        if (g < G4) {
            float4 vn4 = make_float4(cn[j][0], cn[j][1], cn[j][2], cn[j][3]);
            float4 vp4 = make_float4(cp[j][0], cp[j][1], cp[j][2], cp[j][3]);
            *reinterpret_cast<float4*>(&g_colp_neg[(size_t)blockIdx.x * C_DIM + 4 * g]) = vn4;
            *reinterpret_cast<float4*>(&g_colp_pos[(size_t)blockIdx.x * C_DIM + 4 * g]) = vp4;
        }
    }
}

__global__ __launch_bounds__(CR_THREADS)
void col_reduce_kernel(float* __restrict__ out) {
    __shared__ double sd[CR_THREADS / 32];
    __shared__ bool   s_last;
    const int t = threadIdx.x;
    const int c = blockIdx.x * CR_THREADS + t;

    double loc = 0.0;
    if (c < C_DIM) {
        float sn = 0.f, sp = 0.f;
        #pragma unroll 4
        for (int b = 0; b < BLOCKS; ++b) {
            sn += g_colp_neg[(size_t)b * C_DIM + c];
            sp += g_colp_pos[(size_t)b * C_DIM + c];
        }
        if (sn > 0.f && sp > 0.f) {
            const float z = __logf(sn) + 4.f * __logf(sp);
            loc = (double)softplus_f(z);
        }
    }
    #pragma unroll
    for (int o = 16; o > 0; o >>= 1)
        loc += __shfl_down_sync(0xffffffffu, loc, o);
    if ((t & 31) == 0) sd[t >> 5] = loc;
    __syncthreads();
    if (t < 32) {
        double v = (t < CR_THREADS / 32) ? sd[t] : 0.0;
        #pragma unroll
        for (int o = 16; o > 0; o >>= 1)
            v += __shfl_down_sync(0xffffffffu, v, o);
        if (t == 0) {
            atomicAdd(&g_col_loss, v);
            __threadfence();
            unsigned int done = atomicInc(&g_done, 0xffffffffu);
            s_last = (done == CR_BLOCKS - 1);
        }
    }
    __syncthreads();

    // last block folds row losses and writes the scalar output
    if (s_last && t < 32) {
        double rs = 0.0;
        for (int b = t; b < BLOCKS; b += 32)
            rs += (double)g_blk_rowloss[b];
        #pragma unroll
        for (int o = 16; o > 0; o >>= 1)
            rs += __shfl_down_sync(0xffffffffu, rs, o);
        if (t == 0) {
            __threadfence();
            const double col = *((volatile double*)&g_col_loss);
            out[0] = (float)(0.5 * (rs / (double)B_DIM + col / (double)C_DIM));
        }
    }
}

extern "C" void kernel_launch(void* const* d_in, const int* in_sizes, int n_in,
                              void* d_out, int out_size) {
    const float* logits  = (const float*)d_in[0];
    const int*   targets = (const int*)d_in[1];
    float* out = (float*)d_out;

    twl_main_kernel<<<BLOCKS, THREADS>>>(logits, targets);
    col_reduce_kernel<<<CR_BLOCKS, CR_THREADS>>>(out);
}

// round 4
// speedup vs baseline: 1.0970x; 1.0970x over previous
#include <cuda_runtime.h>
#include <math.h>

#define B_DIM   4096
#define C_DIM   5000
#define G4      1250                 // float4 groups per row
#define THREADS 1024
#define BLOCKS  148                  // one persistent block per SM, single wave
#define GPT     2                    // ceil(1250/1024)
#define MAX_LR  28                   // ceil(4096/148)

#define CR_THREADS 128               // col_reduce: 1250 blocks x 128 threads

// per-block column partials (plain stores, no atomics, no pre-zeroing needed)
__device__ float  g_colp_neg[BLOCKS * C_DIM];   // 2.96 MB
__device__ float  g_colp_pos[BLOCKS * C_DIM];   // 2.96 MB
__device__ float  g_blk_rowloss[BLOCKS];
__device__ double g_col_loss;
__device__ unsigned int g_done;

__device__ __forceinline__ float softplus_f(float z) {
    return (z > 20.f) ? z : log1pf(__expf(z));
}

__global__ __launch_bounds__(THREADS, 1)
void twl_main_kernel(const float* __restrict__ logits,
                     const int*   __restrict__ targets) {
    __shared__ float s_n[MAX_LR * 32];
    __shared__ float s_p[MAX_LR * 32];
    __shared__ float s_loss[MAX_LR];

    const int t    = threadIdx.x;
    const int warp = t >> 5;
    const int lane = t & 31;

    if (blockIdx.x == 0 && t == 0) {   // reset accumulators for col_reduce
        g_col_loss = 0.0;
        g_done     = 0u;
    }

    // register-resident column partials: thread t owns float4-groups t, t+1024
    float cn[GPT][4], cp[GPT][4];
    #pragma unroll
    for (int j = 0; j < GPT; ++j)
        #pragma unroll
        for (int k = 0; k < 4; ++k) { cn[j][k] = 0.f; cp[j][k] = 0.f; }

    int lr = 0;
    for (int row = blockIdx.x; row < B_DIM; row += BLOCKS, ++lr) {
        const float4* __restrict__ lrow =
            reinterpret_cast<const float4*>(logits + (size_t)row * C_DIM);
        const int4* __restrict__ trow =
            reinterpret_cast<const int4*>(targets + (size_t)row * C_DIM);

        float rn = 0.f, rp = 0.f;

        #pragma unroll
        for (int j = 0; j < GPT; ++j) {
            const int g = t + j * THREADS;
            if (g < G4) {
                const float4 x  = lrow[g];
                const int4   tg = trow[g];

                #define PROC(XX, TT, K)                                       \
                do {                                                          \
                    const bool pos = ((TT) == 1);                             \
                    const bool neg = ((TT) == 0);                             \
                    const float a  = (XX) * (pos ? -0.25f : 1.0f);            \
                    const float e  = __expf(a);                               \
                    const float en = neg ? e : 0.f;                           \
                    const float ep = pos ? e : 0.f;                           \
                    rn += en; rp += ep;                                       \
                    cn[j][K] += en; cp[j][K] += ep;                           \
                } while (0)

                PROC(x.x, tg.x, 0);
                PROC(x.y, tg.y, 1);
                PROC(x.z, tg.z, 2);
                PROC(x.w, tg.w, 3);
                #undef PROC
            }
        }

        // warp-only reduce (no barrier): rows pipeline freely
        #pragma unroll
        for (int o = 16; o > 0; o >>= 1) {
            rn += __shfl_down_sync(0xffffffffu, rn, o);
            rp += __shfl_down_sync(0xffffffffu, rp, o);
        }
        if (lane == 0) {
            s_n[lr * 32 + warp] = rn;
            s_p[lr * 32 + warp] = rp;
        }
    }

    const int nrows = lr;
    __syncthreads();                  // the ONLY barrier before final reduce

    // warp w finishes row w: 32 warp-partials -> row loss
    if (warp < nrows) {
        float vn = s_n[warp * 32 + lane];
        float vp = s_p[warp * 32 + lane];
        #pragma unroll
        for (int o = 16; o > 0; o >>= 1) {
            vn += __shfl_down_sync(0xffffffffu, vn, o);
            vp += __shfl_down_sync(0xffffffffu, vp, o);
        }
        if (lane == 0) {
            float loss = 0.f;
            if (vn > 0.f && vp > 0.f) {
                const float z = __logf(vn) + 4.f * __logf(vp);
                loss = softplus_f(z);
            }
            s_loss[warp] = loss;
        }
    }
    __syncthreads();
    if (warp == 0) {
        float v = (lane < nrows) ? s_loss[lane] : 0.f;
        #pragma unroll
        for (int o = 16; o > 0; o >>= 1)
            v += __shfl_down_sync(0xffffffffu, v, o);
        if (lane == 0) g_blk_rowloss[blockIdx.x] = v;
    }

    // flush column partials: plain coalesced float4 stores
    #pragma unroll
    for (int j = 0; j < GPT; ++j) {
        const int g = t + j * THREADS;
        if (g < G4) {
            float4 vn4 = make_float4(cn[j][0], cn[j][1], cn[j][2], cn[j][3]);
            float4 vp4 = make_float4(cp[j][0], cp[j][1], cp[j][2], cp[j][3]);
            *reinterpret_cast<float4*>(&g_colp_neg[(size_t)blockIdx.x * C_DIM + 4 * g]) = vn4;
            *reinterpret_cast<float4*>(&g_colp_pos[(size_t)blockIdx.x * C_DIM + 4 * g]) = vp4;
        }
    }
}

// One block per float4 column-group (4 columns). 1250 blocks x 128 threads:
// every thread issues 2-4 independent float4 loads per array -> full MLP,
// data is L2-hot (written by twl_main just before).
__global__ __launch_bounds__(CR_THREADS)
void col_reduce_kernel(float* __restrict__ out) {
    __shared__ float4 s_sn[CR_THREADS / 32];
    __shared__ float4 s_sp[CR_THREADS / 32];
    __shared__ bool   s_last;

    const int t    = threadIdx.x;
    const int warp = t >> 5;
    const int lane = t & 31;
    const int g    = blockIdx.x;            // float4 group: columns 4g..4g+3

    float4 sn = make_float4(0.f, 0.f, 0.f, 0.f);
    float4 sp = make_float4(0.f, 0.f, 0.f, 0.f);

    for (int b = t; b < BLOCKS; b += CR_THREADS) {
        const float4 vn = *reinterpret_cast<const float4*>(
            &g_colp_neg[(size_t)b * C_DIM + 4 * g]);
        const float4 vp = *reinterpret_cast<const float4*>(
            &g_colp_pos[(size_t)b * C_DIM + 4 * g]);
        sn.x += vn.x; sn.y += vn.y; sn.z += vn.z; sn.w += vn.w;
        sp.x += vp.x; sp.y += vp.y; sp.z += vp.z; sp.w += vp.w;
    }

    #pragma unroll
    for (int o = 16; o > 0; o >>= 1) {
        sn.x += __shfl_down_sync(0xffffffffu, sn.x, o);
        sn.y += __shfl_down_sync(0xffffffffu, sn.y, o);
        sn.z += __shfl_down_sync(0xffffffffu, sn.z, o);
        sn.w += __shfl_down_sync(0xffffffffu, sn.w, o);
        sp.x += __shfl_down_sync(0xffffffffu, sp.x, o);
        sp.y += __shfl_down_sync(0xffffffffu, sp.y, o);
        sp.z += __shfl_down_sync(0xffffffffu, sp.z, o);
        sp.w += __shfl_down_sync(0xffffffffu, sp.w, o);
    }
    if (lane == 0) { s_sn[warp] = sn; s_sp[warp] = sp; }
    __syncthreads();

    if (t == 0) {
        float4 an = s_sn[0], ap = s_sp[0];
        #pragma unroll
        for (int w = 1; w < CR_THREADS / 32; ++w) {
            an.x += s_sn[w].x; an.y += s_sn[w].y; an.z += s_sn[w].z; an.w += s_sn[w].w;
            ap.x += s_sp[w].x; ap.y += s_sp[w].y; ap.z += s_sp[w].z; ap.w += s_sp[w].w;
        }
        const float n4[4] = {an.x, an.y, an.z, an.w};
        const float p4[4] = {ap.x, ap.y, ap.z, ap.w};
        double loc = 0.0;
        #pragma unroll
        for (int k = 0; k < 4; ++k) {
            if (n4[k] > 0.f && p4[k] > 0.f) {
                const float z = __logf(n4[k]) + 4.f * __logf(p4[k]);
                loc += (double)softplus_f(z);
            }
        }
        atomicAdd(&g_col_loss, loc);
        __threadfence();
        const unsigned int done = atomicInc(&g_done, 0xffffffffu);
        s_last = (done == (unsigned int)(G4 - 1));
    }
    __syncthreads();

    // last block folds row losses and writes the scalar output
    if (s_last && t < 32) {
        double rs = 0.0;
        for (int b = t; b < BLOCKS; b += 32)
            rs += (double)g_blk_rowloss[b];
        #pragma unroll
        for (int o = 16; o > 0; o >>= 1)
            rs += __shfl_down_sync(0xffffffffu, rs, o);
        if (t == 0) {
            __threadfence();
            const double col = *((volatile double*)&g_col_loss);
            out[0] = (float)(0.5 * (rs / (double)B_DIM + col / (double)C_DIM));
        }
    }
}

extern "C" void kernel_launch(void* const* d_in, const int* in_sizes, int n_in,
                              void* d_out, int out_size) {
    const float* logits  = (const float*)d_in[0];
    const int*   targets = (const int*)d_in[1];
    float* out = (float*)d_out;

    twl_main_kernel<<<BLOCKS, THREADS>>>(logits, targets);
    col_reduce_kernel<<<G4, CR_THREADS>>>(out);
}